// round 10
// baseline (speedup 1.0000x reference)
#include <cuda_runtime.h>
#include <math.h>

#define N_NODES 50000
#define N_EDGES 800000
#define FEAT    128
#define HID     64
#define NSCAN_B 98      // ceil(50000/512)

// ---------------- device scratch (static; 16B-aligned) ----------------
__device__ __align__(16) int      g_src[N_EDGES];
__device__ __align__(16) int      g_dst[N_EDGES];
__device__ __align__(16) int      g_csr[N_EDGES];          // src ids grouped by dst
__device__ __align__(16) int      g_deg[N_NODES];
__device__ __align__(16) int      g_rowptr[N_NODES];
__device__ __align__(16) int      g_cursor[N_NODES];
__device__ __align__(16) int      g_bsum[NSCAN_B + 32];
__device__ __align__(16) float    g_proj[N_NODES * 128];   // [0:64)=rel-proj, [64:128)=root-proj
__device__ __align__(16) float    g_h1[N_NODES * HID];
__device__ __align__(16) float    g_h2[N_NODES * HID];
__device__ __align__(16) float    g_agg3[N_NODES * HID];
__device__ __align__(16) unsigned g_bitmap[(N_NODES + 31) / 32 + 32];
__device__ __align__(16) int      g_list2[N_NODES];
__device__ int      g_n0;
__device__ int      g_m2;
__device__ int      g_ll_e;   // 1 if edge_index is int64, 0 if int32
__device__ int      g_ll_b;   // 1 if batch is int64, 0 if int32
__device__ __align__(16) float    g_sumh3[HID];

// ---------------- dtype detection: int64 little-endian small values => odd words all 0 ------
__global__ void k_detect(const void* __restrict__ ei, const void* __restrict__ batch) {
    __shared__ unsigned se[256], sb[256];
    int t = threadIdx.x;
    const unsigned* we = (const unsigned*)ei;
    unsigned oe = 0;
    for (int i = 1 + 2 * t; i < 4096; i += 512) oe |= we[i];      // within int32 buffer too
    const unsigned* wb = (const unsigned*)batch;
    unsigned ob = 0;
    for (int i = 40001 + 2 * t; i < 50000; i += 512) ob |= wb[i]; // tail: int32 batch != 0 here
    se[t] = oe; sb[t] = ob;
    __syncthreads();
    for (int off = 128; off; off >>= 1) {
        if (t < off) { se[t] |= se[t + off]; sb[t] |= sb[t + off]; }
        __syncthreads();
    }
    if (t == 0) { g_ll_e = (se[0] == 0) ? 1 : 0; g_ll_b = (sb[0] == 0) ? 1 : 0; }
}

__device__ __forceinline__ int load_idx(const void* p, int i, int ll) {
    return ll ? (int)((const long long*)p)[i] : ((const int*)p)[i];
}

// ---------------- prep: zero small state ----------------
__global__ void k_prep0() {
    int i = blockIdx.x * blockDim.x + threadIdx.x;
    if (i < N_NODES) g_deg[i] = 0;
    if (i < (N_NODES + 31) / 32 + 32) g_bitmap[i] = 0u;
    if (i < HID) g_sumh3[i] = 0.f;
    if (i == 0) { g_n0 = 0; g_m2 = 0; }
}

// ---------------- mark graph-0 nodes, count them ----------------
__global__ void k_nodeprep(const void* __restrict__ batch) {
    int ll = g_ll_b;
    int i = blockIdx.x * blockDim.x + threadIdx.x;
    bool z = (i < N_NODES) && (load_idx(batch, i, ll) == 0);
    if (z) atomicOr(&g_bitmap[i >> 5], 1u << (i & 31));
    unsigned m = __ballot_sync(0xFFFFFFFFu, z);
    if ((threadIdx.x & 31) == 0 && m) atomicAdd(&g_n0, __popc(m));
}

// ---------------- edge prep: ->int32, validate, degree histogram, bitmap marking ------------
__global__ void k_edgeprep(const void* __restrict__ ei,
                           const void* __restrict__ batch) {
    int lle = g_ll_e, llb = g_ll_b;
    int e = blockIdx.x * blockDim.x + threadIdx.x;
    if (e >= N_EDGES) return;
    int s = load_idx(ei, e, lle);
    int d = load_idx(ei, N_EDGES + e, lle);
    if ((unsigned)s >= N_NODES || (unsigned)d >= N_NODES) {   // defensive clamp
        g_src[e] = -1; g_dst[e] = -1;
        return;
    }
    g_src[e] = s;
    g_dst[e] = d;
    atomicAdd(&g_deg[d], 1);
    if (load_idx(batch, d, llb) == 0) {
        unsigned bit = 1u << (s & 31);
        if (!(g_bitmap[s >> 5] & bit)) atomicOr(&g_bitmap[s >> 5], bit);
    }
}

// ---------------- exclusive scan of deg -> rowptr (3 kernels) ----------------
__global__ void k_scan1() {             // grid NSCAN_B, block 512
    __shared__ int sm[512];
    int c = blockIdx.x, t = threadIdx.x, idx = c * 512 + t;
    int v = (idx < N_NODES) ? g_deg[idx] : 0;
    sm[t] = v;
    __syncthreads();
    for (int off = 1; off < 512; off <<= 1) {
        int x = (t >= off) ? sm[t - off] : 0;
        __syncthreads();
        sm[t] += x;
        __syncthreads();
    }
    if (idx < N_NODES) g_rowptr[idx] = sm[t] - v;
    if (t == 511) g_bsum[c] = sm[511];
}
__global__ void k_scan2() {             // 1 block, 128 threads
    __shared__ int sm[128];
    int t = threadIdx.x;
    int v = (t < NSCAN_B) ? g_bsum[t] : 0;
    sm[t] = v;
    __syncthreads();
    for (int off = 1; off < 128; off <<= 1) {
        int x = (t >= off) ? sm[t - off] : 0;
        __syncthreads();
        sm[t] += x;
        __syncthreads();
    }
    if (t < NSCAN_B) g_bsum[t] = sm[t] - v;   // exclusive block offsets
}
__global__ void k_scan3() {             // grid NSCAN_B, block 512
    int c = blockIdx.x, idx = c * 512 + threadIdx.x;
    if (idx < N_NODES) {
        int r = g_rowptr[idx] + g_bsum[c];
        g_rowptr[idx] = r;
        g_cursor[idx] = r;
    }
}

// ---------------- CSR fill ----------------
__global__ void k_fill() {
    int e = blockIdx.x * blockDim.x + threadIdx.x;
    if (e >= N_EDGES) return;
    int d = g_dst[e];
    if (d < 0) return;
    int slot = atomicAdd(&g_cursor[d], 1);
    g_csr[slot] = g_src[e];
}

// ---------------- compact bitmap -> list2 ----------------
__global__ void k_list() {
    int i = blockIdx.x * blockDim.x + threadIdx.x;
    bool f = (i < N_NODES) && ((g_bitmap[i >> 5] >> (i & 31)) & 1u);
    unsigned m = __ballot_sync(0xFFFFFFFFu, f);
    int lane = threadIdx.x & 31;
    int base = 0;
    if (lane == 0 && m) base = atomicAdd(&g_m2, __popc(m));
    base = __shfl_sync(0xFFFFFFFFu, base, 0);
    if (f) {
        int rank = __popc(m & ((1u << lane) - 1));
        g_list2[base + rank] = i;
    }
}

// ---------------- fused dual GEMM (static smem, K-tiled):
//   g_proj[i][0:64)  = X[i] @ Wrel,  g_proj[i][64:128) = X[i] @ Wroot
// block = 256 threads, 64 rows/block, 128 cols. Thread: 8 rows x 4 cols. 24KB smem.
template <int K, bool FROM_H1>
__global__ void k_gemm(const float* __restrict__ Xin,
                       const float* __restrict__ Wrel,
                       const float* __restrict__ Wroot) {
    __shared__ float Ws[32][128];
    __shared__ float Xt[32][64];
    const float* X = FROM_H1 ? g_h1 : Xin;

    int tid = threadIdx.x;
    int row0 = blockIdx.x * 64;
    int tx = tid & 31;
    int ty = tid >> 5;
    int jb = tx * 4, rb = ty * 8;

    float acc[8][4];
#pragma unroll
    for (int i = 0; i < 8; i++)
#pragma unroll
        for (int j = 0; j < 4; j++) acc[i][j] = 0.f;

    for (int k0 = 0; k0 < K; k0 += 32) {
        __syncthreads();
        for (int lin = tid; lin < 32 * 64; lin += 256) {
            int k = lin >> 6, j = lin & 63;
            Ws[k][j]      = Wrel[(k0 + k) * 64 + j];
            Ws[k][64 + j] = Wroot[(k0 + k) * 64 + j];
        }
        for (int lin = tid; lin < 64 * 8; lin += 256) {
            int kc = lin >> 6;
            int r  = lin & 63;
            int row = row0 + r;
            float4 v = (row < N_NODES)
                         ? *(const float4*)(X + (size_t)row * K + k0 + kc * 4)
                         : make_float4(0.f, 0.f, 0.f, 0.f);
            Xt[4 * kc + 0][r] = v.x;
            Xt[4 * kc + 1][r] = v.y;
            Xt[4 * kc + 2][r] = v.z;
            Xt[4 * kc + 3][r] = v.w;
        }
        __syncthreads();

#pragma unroll
        for (int k = 0; k < 32; k++) {
            float4 w  = *(float4*)(&Ws[k][jb]);
            float4 a0 = *(float4*)(&Xt[k][rb]);
            float4 a1 = *(float4*)(&Xt[k][rb + 4]);
            float ar[8] = {a0.x, a0.y, a0.z, a0.w, a1.x, a1.y, a1.z, a1.w};
#pragma unroll
            for (int i = 0; i < 8; i++) {
                acc[i][0] += ar[i] * w.x;
                acc[i][1] += ar[i] * w.y;
                acc[i][2] += ar[i] * w.z;
                acc[i][3] += ar[i] * w.w;
            }
        }
    }
#pragma unroll
    for (int i = 0; i < 8; i++) {
        int row = row0 + rb + i;
        if (row < N_NODES)
            *(float4*)(g_proj + (size_t)row * 128 + jb) =
                make_float4(acc[i][0], acc[i][1], acc[i][2], acc[i][3]);
    }
}

// ---------------- gather layer 1 (all nodes): h1 = relu(sum proj_rel[src] + proj_root) -------
__global__ void k_gather1() {
    int node = blockIdx.x * 4 + (threadIdx.x >> 6);
    if (node >= N_NODES) return;
    int j = threadIdx.x & 63;
    int base = g_rowptr[node];
    int cnt  = g_deg[node];
    float acc = 0.f;
    int e = 0;
    for (; e + 4 <= cnt; e += 4) {
        int s0 = g_csr[base + e + 0];
        int s1 = g_csr[base + e + 1];
        int s2 = g_csr[base + e + 2];
        int s3 = g_csr[base + e + 3];
        float a0 = g_proj[(size_t)s0 * 128 + j];
        float a1 = g_proj[(size_t)s1 * 128 + j];
        float a2 = g_proj[(size_t)s2 * 128 + j];
        float a3 = g_proj[(size_t)s3 * 128 + j];
        acc += (a0 + a1) + (a2 + a3);
    }
    for (; e < cnt; e++) acc += g_proj[(size_t)g_csr[base + e] * 128 + j];
    float r = g_proj[(size_t)node * 128 + 64 + j];
    g_h1[(size_t)node * 64 + j] = fmaxf(acc + r, 0.f);
}

// ---------------- gather layer 2 (bitmap nodes only, via list2) ----------------
__global__ void k_gather2() {
    int vidx = blockIdx.x * 4 + (threadIdx.x >> 6);
    if (vidx >= g_m2) return;
    int node = g_list2[vidx];
    int j = threadIdx.x & 63;
    int base = g_rowptr[node];
    int cnt  = g_deg[node];
    float acc = 0.f;
    int e = 0;
    for (; e + 4 <= cnt; e += 4) {
        int s0 = g_csr[base + e + 0];
        int s1 = g_csr[base + e + 1];
        int s2 = g_csr[base + e + 2];
        int s3 = g_csr[base + e + 3];
        float a0 = g_proj[(size_t)s0 * 128 + j];
        float a1 = g_proj[(size_t)s1 * 128 + j];
        float a2 = g_proj[(size_t)s2 * 128 + j];
        float a3 = g_proj[(size_t)s3 * 128 + j];
        acc += (a0 + a1) + (a2 + a3);
    }
    for (; e < cnt; e++) acc += g_proj[(size_t)g_csr[base + e] * 128 + j];
    float r = g_proj[(size_t)node * 128 + 64 + j];
    g_h2[(size_t)node * 64 + j] = fmaxf(acc + r, 0.f);
}

// ---------------- gather layer 3 raw agg (graph-0 nodes only): agg3 = sum h2[src] ------------
__global__ void k_gather3() {
    int node = blockIdx.x * 4 + (threadIdx.x >> 6);
    if (node >= g_n0) return;
    int j = threadIdx.x & 63;
    int base = g_rowptr[node];
    int cnt  = g_deg[node];
    float acc = 0.f;
    for (int e = 0; e < cnt; e++)
        acc += g_h2[(size_t)g_csr[base + e] * 64 + j];
    g_agg3[(size_t)node * 64 + j] = acc;
}

// ---------------- layer 3 projection + pooled sum (graph-0 nodes) ----------------
__global__ void k_l3(const float* __restrict__ Wrel3, const float* __restrict__ Wroot3) {
    __shared__ float Wr[64 * 64];
    __shared__ float Wo[64 * 64];
    __shared__ float ra[4][64], rh[4][64], sh3[4][64];
    int n0 = g_n0;
    int node0 = blockIdx.x * 4;
    if (node0 >= n0) return;
    int tid = threadIdx.x;
    for (int lin = tid; lin < 4096; lin += 256) {
        Wr[lin] = Wrel3[lin];
        Wo[lin] = Wroot3[lin];
    }
    int g = tid >> 6;
    int j = tid & 63;
    int node = node0 + g;
    bool act = node < n0;
    if (act) {
        ra[g][j] = g_agg3[node * 64 + j];
        rh[g][j] = g_h2[node * 64 + j];
    }
    __syncthreads();
    float sum = 0.f;
    if (act) {
#pragma unroll 8
        for (int k = 0; k < 64; k++)
            sum += ra[g][k] * Wr[k * 64 + j] + rh[g][k] * Wo[k * 64 + j];
    }
    sh3[g][j] = act ? fmaxf(sum, 0.f) : 0.f;
    __syncthreads();
    if (tid < 64) {
        float s = sh3[0][tid] + sh3[1][tid] + sh3[2][tid] + sh3[3][tid];
        atomicAdd(&g_sumh3[tid], s);
    }
}

// ---------------- mean -> fc -> softmax -> out[10] ----------------
__global__ void k_out(const float* __restrict__ Wfc, const float* __restrict__ bfc,
                      float* __restrict__ out) {
    __shared__ float mean[64];
    __shared__ float logits[10];
    int t = threadIdx.x;
    float n0f = fmaxf((float)g_n0, 1.f);
    if (t < 64) mean[t] = g_sumh3[t] / n0f;
    __syncthreads();
    if (t < 10) {
        float acc = bfc[t];
        for (int j = 0; j < 64; j++) acc += mean[j] * Wfc[j * 10 + t];
        logits[t] = acc;
    }
    __syncthreads();
    if (t == 0) {
        float mx = -1e30f;
        for (int i = 0; i < 10; i++) mx = fmaxf(mx, logits[i]);
        float e[10], ssum = 0.f;
        for (int i = 0; i < 10; i++) { e[i] = expf(logits[i] - mx); ssum += e[i]; }
        for (int i = 0; i < 10; i++) out[i] = e[i] / ssum;
    }
}

// ---------------- host ----------------
extern "C" void kernel_launch(void* const* d_in, const int* in_sizes, int n_in,
                              void* d_out, int out_size) {
    const float* x      = (const float*)d_in[0];
    const void*  ei     = d_in[1];
    const void*  batch  = d_in[2];
    const float* Wrel1  = (const float*)d_in[3];
    const float* Wroot1 = (const float*)d_in[4];
    const float* Wrel2  = (const float*)d_in[5];
    const float* Wroot2 = (const float*)d_in[6];
    const float* Wrel3  = (const float*)d_in[7];
    const float* Wroot3 = (const float*)d_in[8];
    const float* Wfc    = (const float*)d_in[9];
    const float* bfc    = (const float*)d_in[10];
    float*       out    = (float*)d_out;

    const int NB_NODE  = (N_NODES + 255) / 256;               // 196
    const int NB_EDGE  = (N_EDGES + 255) / 256;               // 3125
    const int NB_GEMM  = (N_NODES + 63) / 64;                 // 782
    const int NB_GATH  = (N_NODES + 3) / 4;                   // 12500

    // dtype sniff + prep + CSR build
    k_detect<<<1, 256>>>(ei, batch);
    k_prep0<<<NB_NODE, 256>>>();
    k_nodeprep<<<NB_NODE, 256>>>(batch);
    k_edgeprep<<<NB_EDGE, 256>>>(ei, batch);
    k_scan1<<<NSCAN_B, 512>>>();
    k_scan2<<<1, 128>>>();
    k_scan3<<<NSCAN_B, 512>>>();
    k_fill<<<NB_EDGE, 256>>>();
    k_list<<<NB_NODE, 256>>>();

    // Layer 1 (full)
    k_gemm<128, false><<<NB_GEMM, 256>>>(x, Wrel1, Wroot1);
    k_gather1<<<NB_GATH, 256>>>();

    // Layer 2 (h2 only at bitmap nodes)
    k_gemm<64, true><<<NB_GEMM, 256>>>(nullptr, Wrel2, Wroot2);
    k_gather2<<<NB_GATH, 256>>>();

    // Layer 3 (graph-0 nodes only)
    k_gather3<<<NB_GATH, 256>>>();
    k_l3<<<NB_GATH, 256>>>(Wrel3, Wroot3);
    k_out<<<1, 64>>>(Wfc, bfc, out);
}

// round 12
// speedup vs baseline: 1.1007x; 1.1007x over previous
#include <cuda_runtime.h>
#include <math.h>

#define N_NODES 50000
#define N_EDGES 800000
#define FEAT    128
#define HID     64
#define NSCAN_B 98      // ceil(50000/512)

typedef unsigned long long u64;

// ---------------- device scratch (static; 16B-aligned) ----------------
__device__ __align__(16) int      g_src[N_EDGES];
__device__ __align__(16) int      g_dst[N_EDGES];
__device__ __align__(16) int      g_csr[N_EDGES];          // src ids grouped by dst
__device__ __align__(16) int      g_deg[N_NODES];
__device__ __align__(16) int      g_rowptr[N_NODES];
__device__ __align__(16) int      g_cursor[N_NODES];
__device__ __align__(16) int      g_bsum[NSCAN_B + 32];
__device__ __align__(16) float    g_proj[N_NODES * 128];   // [0:64)=rel-proj, [64:128)=root-proj
__device__ __align__(16) float    g_h1[N_NODES * HID];
__device__ __align__(16) float    g_h2[N_NODES * HID];
__device__ __align__(16) unsigned g_bitmap[(N_NODES + 31) / 32 + 32];
__device__ __align__(16) int      g_list2[N_NODES];
__device__ int      g_n0;
__device__ int      g_m2;
__device__ int      g_ll_e;   // 1 if edge_index is int64, 0 if int32
__device__ int      g_ll_b;   // 1 if batch is int64, 0 if int32
__device__ __align__(16) float    g_sumh3[HID];

__device__ __forceinline__ int load_idx(const void* p, int i, int ll) {
    return ll ? (int)((const long long*)p)[i] : ((const int*)p)[i];
}

// packed f32x2 helpers
__device__ __forceinline__ u64 pk2(float lo, float hi) {
    u64 r; asm("mov.b64 %0, {%1,%2};" : "=l"(r) : "f"(lo), "f"(hi)); return r;
}
__device__ __forceinline__ void fma2(u64& d, u64 a, u64 b) {
    asm("fma.rn.f32x2 %0, %1, %2, %3;" : "=l"(d) : "l"(a), "l"(b), "l"(d));
}
__device__ __forceinline__ void upk2(float& lo, float& hi, u64 v) {
    asm("mov.b64 {%0,%1}, %2;" : "=f"(lo), "=f"(hi) : "l"(v));
}

// ---------------- dtype detection + n0 boundary search (batch sorted) ----------------
__global__ void k_detect(const void* __restrict__ ei, const void* __restrict__ batch) {
    __shared__ unsigned red[256];
    __shared__ int redi[256];
    __shared__ int llb_s;
    int t = threadIdx.x;
    // edge_index dtype: odd 32-bit words of int64 small values are 0
    red[t] = ((const unsigned*)ei)[1 + 2 * t];
    __syncthreads();
    for (int off = 128; off; off >>= 1) { if (t < off) red[t] |= red[t + off]; __syncthreads(); }
    if (t == 0) g_ll_e = (red[0] == 0) ? 1 : 0;
    __syncthreads();
    // batch dtype: probe odd words in the tail (int32 batch values there are 60-63, nonzero)
    red[t] = ((const unsigned*)batch)[49487 + 2 * t];
    __syncthreads();
    for (int off = 128; off; off >>= 1) { if (t < off) red[t] |= red[t + off]; __syncthreads(); }
    if (t == 0) { int v = (red[0] == 0) ? 1 : 0; g_ll_b = v; llb_s = v; }
    __syncthreads();
    int llb = llb_s;
    // n0 = count of batch==0 (sorted => prefix). Phase 1: coarse probe at stride 196.
    int pos = t * 196;                       // max 49980
    redi[t] = (load_idx(batch, pos, llb) == 0) ? t : 0;
    __syncthreads();
    for (int off = 128; off; off >>= 1) { if (t < off) redi[t] = max(redi[t], redi[t + off]); __syncthreads(); }
    int base = redi[0] * 196;
    __syncthreads();
    // Phase 2: count zeros in (base, base+196]
    int p2 = base + 1 + t;
    redi[t] = (t < 196 && p2 < N_NODES && load_idx(batch, p2, llb) == 0) ? 1 : 0;
    __syncthreads();
    for (int off = 128; off; off >>= 1) { if (t < off) redi[t] += redi[t + off]; __syncthreads(); }
    if (t == 0) g_n0 = base + 1 + redi[0];
}

// ---------------- prep: zero deg/sums, write graph-0 bitmap prefix analytically -------------
__global__ void k_prep0() {
    int i = blockIdx.x * blockDim.x + threadIdx.x;
    if (i < N_NODES) g_deg[i] = 0;
    int nb = (N_NODES + 31) / 32 + 32;
    if (i < nb) {
        int n0 = g_n0;
        int lo = i * 32;
        unsigned v = (lo + 32 <= n0) ? 0xFFFFFFFFu
                   : (lo >= n0 ? 0u : ((1u << (n0 - lo)) - 1u));
        g_bitmap[i] = v;
    }
    if (i < HID) g_sumh3[i] = 0.f;
    if (i == 0) g_m2 = 0;
}

// ---------------- edge prep: ->int32, degree histogram, mark srcs of graph-0 edges ----------
__global__ void k_edgeprep(const void* __restrict__ ei) {
    int lle = g_ll_e;
    int n0  = g_n0;
    int e = blockIdx.x * blockDim.x + threadIdx.x;
    if (e >= N_EDGES) return;
    int s = load_idx(ei, e, lle);
    int d = load_idx(ei, N_EDGES + e, lle);
    if ((unsigned)s >= N_NODES || (unsigned)d >= N_NODES) { g_src[e] = -1; g_dst[e] = -1; return; }
    g_src[e] = s;
    g_dst[e] = d;
    atomicAdd(&g_deg[d], 1);
    if (d < n0) {   // batch sorted: batch[d]==0 <=> d<n0
        unsigned bit = 1u << (s & 31);
        if (!(g_bitmap[s >> 5] & bit)) atomicOr(&g_bitmap[s >> 5], bit);
    }
}

// ---------------- exclusive scan of deg -> rowptr (3 kernels) ----------------
__global__ void k_scan1() {
    __shared__ int sm[512];
    int c = blockIdx.x, t = threadIdx.x, idx = c * 512 + t;
    int v = (idx < N_NODES) ? g_deg[idx] : 0;
    sm[t] = v;
    __syncthreads();
    for (int off = 1; off < 512; off <<= 1) {
        int x = (t >= off) ? sm[t - off] : 0;
        __syncthreads();
        sm[t] += x;
        __syncthreads();
    }
    if (idx < N_NODES) g_rowptr[idx] = sm[t] - v;
    if (t == 511) g_bsum[c] = sm[511];
}
__global__ void k_scan2() {
    __shared__ int sm[128];
    int t = threadIdx.x;
    int v = (t < NSCAN_B) ? g_bsum[t] : 0;
    sm[t] = v;
    __syncthreads();
    for (int off = 1; off < 128; off <<= 1) {
        int x = (t >= off) ? sm[t - off] : 0;
        __syncthreads();
        sm[t] += x;
        __syncthreads();
    }
    if (t < NSCAN_B) g_bsum[t] = sm[t] - v;
}
__global__ void k_scan3() {
    int c = blockIdx.x, idx = c * 512 + threadIdx.x;
    if (idx < N_NODES) {
        int r = g_rowptr[idx] + g_bsum[c];
        g_rowptr[idx] = r;
        g_cursor[idx] = r;
    }
}

// ---------------- CSR fill ----------------
__global__ void k_fill() {
    int e = blockIdx.x * blockDim.x + threadIdx.x;
    if (e >= N_EDGES) return;
    int d = g_dst[e];
    if (d < 0) return;
    int slot = atomicAdd(&g_cursor[d], 1);
    g_csr[slot] = g_src[e];
}

// ---------------- compact bitmap -> list2 ----------------
__global__ void k_list() {
    int i = blockIdx.x * blockDim.x + threadIdx.x;
    bool f = (i < N_NODES) && ((g_bitmap[i >> 5] >> (i & 31)) & 1u);
    unsigned m = __ballot_sync(0xFFFFFFFFu, f);
    int lane = threadIdx.x & 31;
    int base = 0;
    if (lane == 0 && m) base = atomicAdd(&g_m2, __popc(m));
    base = __shfl_sync(0xFFFFFFFFu, base, 0);
    if (f) {
        int rank = __popc(m & ((1u << lane) - 1));
        g_list2[base + rank] = i;
    }
}

// ---------------- fused dual GEMM, packed f32x2 mainloop ----------------
// Thread tile: 8 rows x 4 cols as 4 row-pairs (f32x2) x 4 cols.
template <int K, bool FROM_H1>
__global__ void k_gemm(const float* __restrict__ Xin,
                       const float* __restrict__ Wrel,
                       const float* __restrict__ Wroot) {
    __shared__ __align__(16) float Ws[32][128];
    __shared__ __align__(16) float Xt[32][64];
    const float* X = FROM_H1 ? g_h1 : Xin;

    int tid = threadIdx.x;
    int row0 = blockIdx.x * 64;
    int tx = tid & 31;
    int ty = tid >> 5;
    int jb = tx * 4, rb = ty * 8;

    u64 accp[4][4];
#pragma unroll
    for (int rp = 0; rp < 4; rp++)
#pragma unroll
        for (int c = 0; c < 4; c++) accp[rp][c] = 0ull;

    for (int k0 = 0; k0 < K; k0 += 32) {
        __syncthreads();
        for (int lin = tid; lin < 32 * 64; lin += 256) {
            int k = lin >> 6, j = lin & 63;
            Ws[k][j]      = Wrel[(k0 + k) * 64 + j];
            Ws[k][64 + j] = Wroot[(k0 + k) * 64 + j];
        }
        for (int lin = tid; lin < 64 * 8; lin += 256) {
            int kc = lin >> 6;
            int r  = lin & 63;
            int row = row0 + r;
            float4 v = (row < N_NODES)
                         ? *(const float4*)(X + (size_t)row * K + k0 + kc * 4)
                         : make_float4(0.f, 0.f, 0.f, 0.f);
            Xt[4 * kc + 0][r] = v.x;
            Xt[4 * kc + 1][r] = v.y;
            Xt[4 * kc + 2][r] = v.z;
            Xt[4 * kc + 3][r] = v.w;
        }
        __syncthreads();

#pragma unroll
        for (int k = 0; k < 32; k++) {
            float4 w = *(float4*)(&Ws[k][jb]);
            u64 wx = pk2(w.x, w.x), wy = pk2(w.y, w.y);
            u64 wz = pk2(w.z, w.z), ww = pk2(w.w, w.w);
            const u64* xp = (const u64*)(&Xt[k][rb]);   // rb even -> 8B aligned
            u64 a0 = xp[0], a1 = xp[1], a2 = xp[2], a3 = xp[3];
            fma2(accp[0][0], a0, wx); fma2(accp[0][1], a0, wy);
            fma2(accp[0][2], a0, wz); fma2(accp[0][3], a0, ww);
            fma2(accp[1][0], a1, wx); fma2(accp[1][1], a1, wy);
            fma2(accp[1][2], a1, wz); fma2(accp[1][3], a1, ww);
            fma2(accp[2][0], a2, wx); fma2(accp[2][1], a2, wy);
            fma2(accp[2][2], a2, wz); fma2(accp[2][3], a2, ww);
            fma2(accp[3][0], a3, wx); fma2(accp[3][1], a3, wy);
            fma2(accp[3][2], a3, wz); fma2(accp[3][3], a3, ww);
        }
    }
#pragma unroll
    for (int rp = 0; rp < 4; rp++) {
        float l0, h0, l1, h1, l2, h2, l3, h3;
        upk2(l0, h0, accp[rp][0]);
        upk2(l1, h1, accp[rp][1]);
        upk2(l2, h2, accp[rp][2]);
        upk2(l3, h3, accp[rp][3]);
        int r0 = row0 + rb + 2 * rp;
        int r1 = r0 + 1;
        if (r0 < N_NODES)
            *(float4*)(g_proj + (size_t)r0 * 128 + jb) = make_float4(l0, l1, l2, l3);
        if (r1 < N_NODES)
            *(float4*)(g_proj + (size_t)r1 * 128 + jb) = make_float4(h0, h1, h2, h3);
    }
}

// ---------------- gather layer 1 (all nodes): h1 = relu(sum proj_rel[src] + proj_root) ------
__global__ void k_gather1() {
    int node = blockIdx.x * 4 + (threadIdx.x >> 6);
    if (node >= N_NODES) return;
    int j = threadIdx.x & 63;
    int base = g_rowptr[node];
    int cnt  = g_deg[node];
    float acc = 0.f;
    int e = 0;
    for (; e + 4 <= cnt; e += 4) {
        int s0 = g_csr[base + e + 0];
        int s1 = g_csr[base + e + 1];
        int s2 = g_csr[base + e + 2];
        int s3 = g_csr[base + e + 3];
        float a0 = g_proj[(size_t)s0 * 128 + j];
        float a1 = g_proj[(size_t)s1 * 128 + j];
        float a2 = g_proj[(size_t)s2 * 128 + j];
        float a3 = g_proj[(size_t)s3 * 128 + j];
        acc += (a0 + a1) + (a2 + a3);
    }
    for (; e < cnt; e++) acc += g_proj[(size_t)g_csr[base + e] * 128 + j];
    float r = g_proj[(size_t)node * 128 + 64 + j];
    g_h1[(size_t)node * 64 + j] = fmaxf(acc + r, 0.f);
}

// ---------------- gather layer 2 (bitmap nodes only, via list2) ----------------
__global__ void k_gather2() {
    int vidx = blockIdx.x * 4 + (threadIdx.x >> 6);
    if (vidx >= g_m2) return;
    int node = g_list2[vidx];
    int j = threadIdx.x & 63;
    int base = g_rowptr[node];
    int cnt  = g_deg[node];
    float acc = 0.f;
    int e = 0;
    for (; e + 4 <= cnt; e += 4) {
        int s0 = g_csr[base + e + 0];
        int s1 = g_csr[base + e + 1];
        int s2 = g_csr[base + e + 2];
        int s3 = g_csr[base + e + 3];
        float a0 = g_proj[(size_t)s0 * 128 + j];
        float a1 = g_proj[(size_t)s1 * 128 + j];
        float a2 = g_proj[(size_t)s2 * 128 + j];
        float a3 = g_proj[(size_t)s3 * 128 + j];
        acc += (a0 + a1) + (a2 + a3);
    }
    for (; e < cnt; e++) acc += g_proj[(size_t)g_csr[base + e] * 128 + j];
    float r = g_proj[(size_t)node * 128 + 64 + j];
    g_h2[(size_t)node * 64 + j] = fmaxf(acc + r, 0.f);
}

// ---------------- layer 3: fused gather (agg over graph-0 in-edges) + projection + pool -----
__global__ void k_l3(const float* __restrict__ Wrel3, const float* __restrict__ Wroot3) {
    __shared__ float Wr[64 * 64];
    __shared__ float Wo[64 * 64];
    __shared__ float ra[4][64], rh[4][64], sh3[4][64];
    int n0 = g_n0;
    int node0 = blockIdx.x * 4;
    if (node0 >= n0) return;
    int tid = threadIdx.x;
    for (int lin = tid; lin < 4096; lin += 256) {
        Wr[lin] = Wrel3[lin];
        Wo[lin] = Wroot3[lin];
    }
    int g = tid >> 6;
    int j = tid & 63;
    int node = node0 + g;
    bool act = node < n0;
    if (act) {
        int base = g_rowptr[node];
        int cnt  = g_deg[node];
        float acc = 0.f;
        for (int e = 0; e < cnt; e++)
            acc += g_h2[(size_t)g_csr[base + e] * 64 + j];
        ra[g][j] = acc;
        rh[g][j] = g_h2[(size_t)node * 64 + j];
    }
    __syncthreads();
    float sum = 0.f;
    if (act) {
#pragma unroll 8
        for (int k = 0; k < 64; k++)
            sum += ra[g][k] * Wr[k * 64 + j] + rh[g][k] * Wo[k * 64 + j];
    }
    sh3[g][j] = act ? fmaxf(sum, 0.f) : 0.f;
    __syncthreads();
    if (tid < 64) {
        float s = sh3[0][tid] + sh3[1][tid] + sh3[2][tid] + sh3[3][tid];
        atomicAdd(&g_sumh3[tid], s);
    }
}

// ---------------- mean -> fc -> softmax -> out[10] ----------------
__global__ void k_out(const float* __restrict__ Wfc, const float* __restrict__ bfc,
                      float* __restrict__ out) {
    __shared__ float mean[64];
    __shared__ float logits[10];
    int t = threadIdx.x;
    float n0f = fmaxf((float)g_n0, 1.f);
    if (t < 64) mean[t] = g_sumh3[t] / n0f;
    __syncthreads();
    if (t < 10) {
        float acc = bfc[t];
        for (int j = 0; j < 64; j++) acc += mean[j] * Wfc[j * 10 + t];
        logits[t] = acc;
    }
    __syncthreads();
    if (t == 0) {
        float mx = -1e30f;
        for (int i = 0; i < 10; i++) mx = fmaxf(mx, logits[i]);
        float e[10], ssum = 0.f;
        for (int i = 0; i < 10; i++) { e[i] = expf(logits[i] - mx); ssum += e[i]; }
        for (int i = 0; i < 10; i++) out[i] = e[i] / ssum;
    }
}

// ---------------- host ----------------
extern "C" void kernel_launch(void* const* d_in, const int* in_sizes, int n_in,
                              void* d_out, int out_size) {
    const float* x      = (const float*)d_in[0];
    const void*  ei     = d_in[1];
    const void*  batch  = d_in[2];
    const float* Wrel1  = (const float*)d_in[3];
    const float* Wroot1 = (const float*)d_in[4];
    const float* Wrel2  = (const float*)d_in[5];
    const float* Wroot2 = (const float*)d_in[6];
    const float* Wrel3  = (const float*)d_in[7];
    const float* Wroot3 = (const float*)d_in[8];
    const float* Wfc    = (const float*)d_in[9];
    const float* bfc    = (const float*)d_in[10];
    float*       out    = (float*)d_out;

    const int NB_NODE  = (N_NODES + 255) / 256;               // 196
    const int NB_EDGE  = (N_EDGES + 255) / 256;               // 3125
    const int NB_GEMM  = (N_NODES + 63) / 64;                 // 782
    const int NB_GATH  = (N_NODES + 3) / 4;                   // 12500

    // dtype sniff + n0 + prep + CSR build
    k_detect<<<1, 256>>>(ei, batch);
    k_prep0<<<NB_NODE, 256>>>();
    k_edgeprep<<<NB_EDGE, 256>>>(ei);
    k_scan1<<<NSCAN_B, 512>>>();
    k_scan2<<<1, 128>>>();
    k_scan3<<<NSCAN_B, 512>>>();
    k_fill<<<NB_EDGE, 256>>>();
    k_list<<<NB_NODE, 256>>>();

    // Layer 1 (full)
    k_gemm<128, false><<<NB_GEMM, 256>>>(x, Wrel1, Wroot1);
    k_gather1<<<NB_GATH, 256>>>();

    // Layer 2 (h2 only at bitmap nodes)
    k_gemm<64, true><<<NB_GEMM, 256>>>(nullptr, Wrel2, Wroot2);
    k_gather2<<<NB_GATH, 256>>>();

    // Layer 3 (graph-0 nodes only, gather fused into projection)
    k_l3<<<NB_GATH, 256>>>(Wrel3, Wroot3);
    k_out<<<1, 64>>>(Wfc, bfc, out);
}

// round 16
// speedup vs baseline: 1.1717x; 1.0645x over previous
#include <cuda_runtime.h>
#include <math.h>

#define N_NODES 50000
#define N_EDGES 800000
#define FEAT    128
#define HID     64
#define NSCAN_B 98      // ceil(50000/512)
#define NB_EDGE 3125    // edge blocks @256
#define NB_GEMM 782     // gemm blocks (64 rows each)

typedef unsigned long long u64;

// ---------------- device scratch (static; 16B-aligned) ----------------
__device__ __align__(16) int      g_src[N_EDGES];
__device__ __align__(16) int      g_dst[N_EDGES];
__device__ __align__(16) int      g_csr[N_EDGES];
__device__ __align__(16) int      g_deg[N_NODES];
__device__ __align__(16) int      g_rowptr[N_NODES];
__device__ __align__(16) int      g_cursor[N_NODES];
__device__ __align__(16) int      g_bsum[NSCAN_B + 32];
__device__ __align__(16) float    g_proj[N_NODES * 128];   // [0:64) rel, [64:128) root
__device__ __align__(16) float    g_h1[N_NODES * HID];
__device__ __align__(16) float    g_h2[N_NODES * HID];
__device__ __align__(16) unsigned g_bitmap[(N_NODES + 31) / 32 + 32];
__device__ __align__(16) int      g_list2[N_NODES];
__device__ int      g_n0;
__device__ int      g_m2;
__device__ int      g_ll_e;
__device__ int      g_ll_b;
__device__ __align__(16) float    g_sumh3[HID];

__device__ __forceinline__ int load_idx(const void* p, int i, int ll) {
    return ll ? (int)((const long long*)p)[i] : ((const int*)p)[i];
}

// packed f32x2 helpers
__device__ __forceinline__ u64 pk2(float lo, float hi) {
    u64 r; asm("mov.b64 %0, {%1,%2};" : "=l"(r) : "f"(lo), "f"(hi)); return r;
}
__device__ __forceinline__ void fma2(u64& d, u64 a, u64 b) {
    asm("fma.rn.f32x2 %0, %1, %2, %3;" : "=l"(d) : "l"(a), "l"(b), "l"(d));
}
__device__ __forceinline__ void upk2(float& lo, float& hi, u64 v) {
    asm("mov.b64 {%0,%1}, %2;" : "=f"(lo), "=f"(hi) : "l"(v));
}

// ---------------- init: block 0 = dtype sniff + n0 search; blocks 1.. zero state ------------
__global__ void k_init(const void* __restrict__ ei, const void* __restrict__ batch) {
    int t = threadIdx.x;
    if (blockIdx.x == 0) {
        __shared__ unsigned red[256];
        __shared__ int redi[256];
        __shared__ int llb_s;
        // edge_index dtype
        red[t] = ((const unsigned*)ei)[1 + 2 * t];
        __syncthreads();
        for (int off = 128; off; off >>= 1) { if (t < off) red[t] |= red[t + off]; __syncthreads(); }
        if (t == 0) g_ll_e = (red[0] == 0) ? 1 : 0;
        __syncthreads();
        // batch dtype (tail odd words)
        red[t] = ((const unsigned*)batch)[49487 + 2 * t];
        __syncthreads();
        for (int off = 128; off; off >>= 1) { if (t < off) red[t] |= red[t + off]; __syncthreads(); }
        if (t == 0) { int v = (red[0] == 0) ? 1 : 0; g_ll_b = v; llb_s = v; }
        __syncthreads();
        int llb = llb_s;
        // n0 boundary (batch sorted): coarse stride-196 probe
        int pos = t * 196;
        redi[t] = (load_idx(batch, pos, llb) == 0) ? t : 0;
        __syncthreads();
        for (int off = 128; off; off >>= 1) { if (t < off) redi[t] = max(redi[t], redi[t + off]); __syncthreads(); }
        int base = redi[0] * 196;
        __syncthreads();
        int p2 = base + 1 + t;
        redi[t] = (t < 196 && p2 < N_NODES && load_idx(batch, p2, llb) == 0) ? 1 : 0;
        __syncthreads();
        for (int off = 128; off; off >>= 1) { if (t < off) redi[t] += redi[t + off]; __syncthreads(); }
        if (t == 0) g_n0 = base + 1 + redi[0];
    } else {
        int i = (blockIdx.x - 1) * 256 + t;
        if (i < N_NODES) g_deg[i] = 0;
        if (i < (N_NODES + 31) / 32 + 32) g_bitmap[i] = 0u;
        if (i < HID) g_sumh3[i] = 0.f;
        if (i == 0) g_m2 = 0;
    }
}

// ---------------- edge prep: ->int32, degree histogram, mark srcs of graph-0 edges ----------
__global__ void k_edgeprep(const void* __restrict__ ei) {
    int lle = g_ll_e;
    int n0  = g_n0;
    int e = blockIdx.x * blockDim.x + threadIdx.x;
    if (e >= N_EDGES) return;
    int s = load_idx(ei, e, lle);
    int d = load_idx(ei, N_EDGES + e, lle);
    if ((unsigned)s >= N_NODES || (unsigned)d >= N_NODES) { g_src[e] = -1; g_dst[e] = -1; return; }
    g_src[e] = s;
    g_dst[e] = d;
    atomicAdd(&g_deg[d], 1);
    if (d < n0) {
        unsigned bit = 1u << (s & 31);
        if (!(g_bitmap[s >> 5] & bit)) atomicOr(&g_bitmap[s >> 5], bit);
    }
}

// ---------------- scan stage 1: per-block exclusive scan of degrees ----------------
__global__ void k_scan1() {
    __shared__ int sm[512];
    int c = blockIdx.x, t = threadIdx.x, idx = c * 512 + t;
    int v = (idx < N_NODES) ? g_deg[idx] : 0;
    sm[t] = v;
    __syncthreads();
    for (int off = 1; off < 512; off <<= 1) {
        int x = (t >= off) ? sm[t - off] : 0;
        __syncthreads();
        sm[t] += x;
        __syncthreads();
    }
    if (idx < N_NODES) g_rowptr[idx] = sm[t] - v;
    if (t == 511) g_bsum[c] = sm[511];
}

// ---------------- scan stage 2+3 + list compaction, fused by block range -------------------
__global__ void k_scan23list() {
    int t = threadIdx.x;
    if (blockIdx.x < NSCAN_B) {
        __shared__ int sm[128];
        int c = blockIdx.x;
        sm[t < 128 ? t : 0] = 0;
        __syncthreads();
        if (t < 128) sm[t] = (t < c) ? g_bsum[t] : 0;
        __syncthreads();
        for (int off = 64; off; off >>= 1) {
            if (t < off) sm[t] += sm[t + off];
            __syncthreads();
        }
        int offset = sm[0];
        int idx = c * 512 + t;
        if (idx < N_NODES) {
            int r = g_rowptr[idx] + offset;
            g_rowptr[idx] = r;
            g_cursor[idx] = r;
        }
    } else {
        int n0 = g_n0;
        int i = (blockIdx.x - NSCAN_B) * 512 + t;
        bool f = (i < N_NODES) && (i < n0 || ((g_bitmap[i >> 5] >> (i & 31)) & 1u));
        unsigned m = __ballot_sync(0xFFFFFFFFu, f);
        int lane = t & 31;
        int base = 0;
        if (lane == 0 && m) base = atomicAdd(&g_m2, __popc(m));
        base = __shfl_sync(0xFFFFFFFFu, base, 0);
        if (f) {
            int rank = __popc(m & ((1u << lane) - 1));
            g_list2[base + rank] = i;
        }
    }
}

// ---------------- GEMM body (device fn): proj[i][0:64)=X@Wrel, [64:128)=X@Wroot -------------
template <int K, bool FROM_H1>
__device__ __forceinline__ void dev_gemm(int bid, const float* __restrict__ Xin,
                                         const float* __restrict__ Wrel,
                                         const float* __restrict__ Wroot) {
    __shared__ __align__(16) float Ws[32][128];
    __shared__ __align__(16) float Xt[32][64];
    const float* X = FROM_H1 ? g_h1 : Xin;

    int tid = threadIdx.x;
    int row0 = bid * 64;
    int tx = tid & 31;
    int ty = tid >> 5;
    int jb = tx * 4, rb = ty * 8;

    u64 accp[4][4];
#pragma unroll
    for (int rp = 0; rp < 4; rp++)
#pragma unroll
        for (int c = 0; c < 4; c++) accp[rp][c] = 0ull;

    for (int k0 = 0; k0 < K; k0 += 32) {
        __syncthreads();
        for (int lin = tid; lin < 32 * 64; lin += 256) {
            int k = lin >> 6, j = lin & 63;
            Ws[k][j]      = Wrel[(k0 + k) * 64 + j];
            Ws[k][64 + j] = Wroot[(k0 + k) * 64 + j];
        }
        for (int lin = tid; lin < 64 * 8; lin += 256) {
            int kc = lin >> 6;
            int r  = lin & 63;
            int row = row0 + r;
            float4 v = (row < N_NODES)
                         ? *(const float4*)(X + (size_t)row * K + k0 + kc * 4)
                         : make_float4(0.f, 0.f, 0.f, 0.f);
            Xt[4 * kc + 0][r] = v.x;
            Xt[4 * kc + 1][r] = v.y;
            Xt[4 * kc + 2][r] = v.z;
            Xt[4 * kc + 3][r] = v.w;
        }
        __syncthreads();

#pragma unroll
        for (int k = 0; k < 32; k++) {
            float4 w = *(float4*)(&Ws[k][jb]);
            u64 wx = pk2(w.x, w.x), wy = pk2(w.y, w.y);
            u64 wz = pk2(w.z, w.z), ww = pk2(w.w, w.w);
            const u64* xp = (const u64*)(&Xt[k][rb]);
            u64 a0 = xp[0], a1 = xp[1], a2 = xp[2], a3 = xp[3];
            fma2(accp[0][0], a0, wx); fma2(accp[0][1], a0, wy);
            fma2(accp[0][2], a0, wz); fma2(accp[0][3], a0, ww);
            fma2(accp[1][0], a1, wx); fma2(accp[1][1], a1, wy);
            fma2(accp[1][2], a1, wz); fma2(accp[1][3], a1, ww);
            fma2(accp[2][0], a2, wx); fma2(accp[2][1], a2, wy);
            fma2(accp[2][2], a2, wz); fma2(accp[2][3], a2, ww);
            fma2(accp[3][0], a3, wx); fma2(accp[3][1], a3, wy);
            fma2(accp[3][2], a3, wz); fma2(accp[3][3], a3, ww);
        }
    }
#pragma unroll
    for (int rp = 0; rp < 4; rp++) {
        float l0, h0, l1, h1, l2, h2, l3, h3;
        upk2(l0, h0, accp[rp][0]);
        upk2(l1, h1, accp[rp][1]);
        upk2(l2, h2, accp[rp][2]);
        upk2(l3, h3, accp[rp][3]);
        int r0 = row0 + rb + 2 * rp;
        int r1 = r0 + 1;
        if (r0 < N_NODES)
            *(float4*)(g_proj + (size_t)r0 * 128 + jb) = make_float4(l0, l1, l2, l3);
        if (r1 < N_NODES)
            *(float4*)(g_proj + (size_t)r1 * 128 + jb) = make_float4(h0, h1, h2, h3);
    }
}

// ---------------- mega: CSR fill (blocks 0..3124) || GEMM1 (blocks 3125..3906) --------------
__global__ void k_mega(const float* __restrict__ x,
                       const float* __restrict__ Wrel1,
                       const float* __restrict__ Wroot1) {
    if (blockIdx.x < NB_EDGE) {
        int e = blockIdx.x * 256 + threadIdx.x;
        if (e >= N_EDGES) return;
        int d = g_dst[e];
        if (d < 0) return;
        int slot = atomicAdd(&g_cursor[d], 1);
        g_csr[slot] = g_src[e];
    } else {
        dev_gemm<128, false>(blockIdx.x - NB_EDGE, x, Wrel1, Wroot1);
    }
}

// ---------------- GEMM2 wrapper ----------------
__global__ void k_gemm2(const float* __restrict__ Wrel2, const float* __restrict__ Wroot2) {
    dev_gemm<64, true>(blockIdx.x, nullptr, Wrel2, Wroot2);
}

// ---------------- gather layer 1 (all nodes) ----------------
__global__ void k_gather1() {
    int node = blockIdx.x * 4 + (threadIdx.x >> 6);
    if (node >= N_NODES) return;
    int j = threadIdx.x & 63;
    int base = g_rowptr[node];
    int cnt  = g_deg[node];
    float acc = 0.f;
    int e = 0;
    for (; e + 4 <= cnt; e += 4) {
        int s0 = g_csr[base + e + 0];
        int s1 = g_csr[base + e + 1];
        int s2 = g_csr[base + e + 2];
        int s3 = g_csr[base + e + 3];
        float a0 = g_proj[(size_t)s0 * 128 + j];
        float a1 = g_proj[(size_t)s1 * 128 + j];
        float a2 = g_proj[(size_t)s2 * 128 + j];
        float a3 = g_proj[(size_t)s3 * 128 + j];
        acc += (a0 + a1) + (a2 + a3);
    }
    for (; e < cnt; e++) acc += g_proj[(size_t)g_csr[base + e] * 128 + j];
    float r = g_proj[(size_t)node * 128 + 64 + j];
    g_h1[(size_t)node * 64 + j] = fmaxf(acc + r, 0.f);
}

// ---------------- gather layer 2 (list2 nodes) ----------------
__global__ void k_gather2() {
    int vidx = blockIdx.x * 4 + (threadIdx.x >> 6);
    if (vidx >= g_m2) return;
    int node = g_list2[vidx];
    int j = threadIdx.x & 63;
    int base = g_rowptr[node];
    int cnt  = g_deg[node];
    float acc = 0.f;
    int e = 0;
    for (; e + 4 <= cnt; e += 4) {
        int s0 = g_csr[base + e + 0];
        int s1 = g_csr[base + e + 1];
        int s2 = g_csr[base + e + 2];
        int s3 = g_csr[base + e + 3];
        float a0 = g_proj[(size_t)s0 * 128 + j];
        float a1 = g_proj[(size_t)s1 * 128 + j];
        float a2 = g_proj[(size_t)s2 * 128 + j];
        float a3 = g_proj[(size_t)s3 * 128 + j];
        acc += (a0 + a1) + (a2 + a3);
    }
    for (; e < cnt; e++) acc += g_proj[(size_t)g_csr[base + e] * 128 + j];
    float r = g_proj[(size_t)node * 128 + 64 + j];
    g_h2[(size_t)node * 64 + j] = fmaxf(acc + r, 0.f);
}

// ---------------- layer 3: fused gather + projection + pool (graph-0 nodes) -----------------
__global__ void k_l3(const float* __restrict__ Wrel3, const float* __restrict__ Wroot3) {
    __shared__ float Wr[64 * 64];
    __shared__ float Wo[64 * 64];
    __shared__ float ra[4][64], rh[4][64], sh3[4][64];
    int n0 = g_n0;
    int node0 = blockIdx.x * 4;
    if (node0 >= n0) return;
    int tid = threadIdx.x;
    for (int lin = tid; lin < 4096; lin += 256) {
        Wr[lin] = Wrel3[lin];
        Wo[lin] = Wroot3[lin];
    }
    int g = tid >> 6;
    int j = tid & 63;
    int node = node0 + g;
    bool act = node < n0;
    if (act) {
        int base = g_rowptr[node];
        int cnt  = g_deg[node];
        float acc = 0.f;
        for (int e = 0; e < cnt; e++)
            acc += g_h2[(size_t)g_csr[base + e] * 64 + j];
        ra[g][j] = acc;
        rh[g][j] = g_h2[(size_t)node * 64 + j];
    }
    __syncthreads();
    float sum = 0.f;
    if (act) {
#pragma unroll 8
        for (int k = 0; k < 64; k++)
            sum += ra[g][k] * Wr[k * 64 + j] + rh[g][k] * Wo[k * 64 + j];
    }
    sh3[g][j] = act ? fmaxf(sum, 0.f) : 0.f;
    __syncthreads();
    if (tid < 64) {
        float s = sh3[0][tid] + sh3[1][tid] + sh3[2][tid] + sh3[3][tid];
        atomicAdd(&g_sumh3[tid], s);
    }
}

// ---------------- mean -> fc -> softmax -> out[10] ----------------
__global__ void k_out(const float* __restrict__ Wfc, const float* __restrict__ bfc,
                      float* __restrict__ out) {
    __shared__ float mean[64];
    __shared__ float logits[10];
    int t = threadIdx.x;
    float n0f = fmaxf((float)g_n0, 1.f);
    if (t < 64) mean[t] = g_sumh3[t] / n0f;
    __syncthreads();
    if (t < 10) {
        float acc = bfc[t];
        for (int j = 0; j < 64; j++) acc += mean[j] * Wfc[j * 10 + t];
        logits[t] = acc;
    }
    __syncthreads();
    if (t == 0) {
        float mx = -1e30f;
        for (int i = 0; i < 10; i++) mx = fmaxf(mx, logits[i]);
        float e[10], ssum = 0.f;
        for (int i = 0; i < 10; i++) { e[i] = expf(logits[i] - mx); ssum += e[i]; }
        for (int i = 0; i < 10; i++) out[i] = e[i] / ssum;
    }
}

// ---------------- host ----------------
extern "C" void kernel_launch(void* const* d_in, const int* in_sizes, int n_in,
                              void* d_out, int out_size) {
    const float* x      = (const float*)d_in[0];
    const void*  ei     = d_in[1];
    const void*  batch  = d_in[2];
    const float* Wrel1  = (const float*)d_in[3];
    const float* Wroot1 = (const float*)d_in[4];
    const float* Wrel2  = (const float*)d_in[5];
    const float* Wroot2 = (const float*)d_in[6];
    const float* Wrel3  = (const float*)d_in[7];
    const float* Wroot3 = (const float*)d_in[8];
    const float* Wfc    = (const float*)d_in[9];
    const float* bfc    = (const float*)d_in[10];
    float*       out    = (float*)d_out;

    const int NB_GATH = (N_NODES + 3) / 4;   // 12500

    k_init<<<197, 256>>>(ei, batch);                 // detect+n0 || zero
    k_edgeprep<<<NB_EDGE, 256>>>(ei);                // dtype-dispatched, deg histogram
    k_scan1<<<NSCAN_B, 512>>>();                     // per-block scan
    k_scan23list<<<2 * NSCAN_B, 512>>>();            // offsets+cursor || list compaction
    k_mega<<<NB_EDGE + NB_GEMM, 256>>>(x, Wrel1, Wroot1);   // CSR fill || GEMM1
    k_gather1<<<NB_GATH, 256>>>();
    k_gemm2<<<NB_GEMM, 256>>>(Wrel2, Wroot2);
    k_gather2<<<NB_GATH, 256>>>();
    k_l3<<<NB_GATH, 256>>>(Wrel3, Wroot3);
    k_out<<<1, 64>>>(Wfc, bfc, out);
}